// round 1
// baseline (speedup 1.0000x reference)
#include <cuda_runtime.h>
#include <math.h>

#define TT   5        // edge types
#define CC   2        // channels
#define NN   4096     // nodes
#define EE   150000   // edges per type
#define WIN  512
#define WOUT 128
#define NT   1024     // targets
#define NCLS 16

// ---------------- scratch (static device memory only; no allocations) ----------------
__device__ int   g_cnt[TT * NN];
__device__ int   g_rowptr[TT * (NN + 1)];
__device__ int   g_cursor[TT * NN];
__device__ int   g_dst[TT * EE];
__device__ float g_valv[TT * EE];
__device__ float g_f1[CC * TT], g_f2[CC * TT], g_f3[CC * TT];
__device__ __align__(16) float g_XW[NN * WOUT];
__device__ __align__(16) float g_Y3[CC * NN * WOUT];
__device__ __align__(16) float g_Y2[CC * NN * WOUT];
__device__ float g_rs[TT * NN];
__device__ float g_s2[CC * NN];
__device__ float g_t3[CC * NN];
__device__ float g_u [CC * NN];
__device__ __align__(16) float g_Xt[NT * CC * WOUT];

// ---------------- kernels ----------------

__global__ void zero_k() {
    int i = blockIdx.x * blockDim.x + threadIdx.x;
    if (i < TT * NN) g_cnt[i] = 0;
}

// softmax over the 5 edge types for each (matrix, channel)
__global__ void softmax_k(const float* w1, const float* w2, const float* w3) {
    int tid = threadIdx.x;
    if (tid < 6) {
        int m = tid >> 1, c = tid & 1;
        const float* w = (m == 0 ? w1 : (m == 1 ? w2 : w3)) + c * TT;
        float*       f = (m == 0 ? g_f1 : (m == 1 ? g_f2 : g_f3)) + c * TT;
        float mx = w[0];
        for (int j = 1; j < TT; j++) mx = fmaxf(mx, w[j]);
        float e[TT], s = 0.f;
        for (int j = 0; j < TT; j++) { e[j] = expf(w[j] - mx); s += e[j]; }
        float inv = 1.f / s;
        for (int j = 0; j < TT; j++) f[j] = e[j] * inv;
    }
}

__global__ void count_k(const int* __restrict__ edge_index) {
    int gid = blockIdx.x * blockDim.x + threadIdx.x;
    if (gid >= TT * EE) return;
    int j = gid / EE, e = gid - j * EE;
    int src = edge_index[j * 2 * EE + e];  // edge_index[j][0][e]
    atomicAdd(&g_cnt[j * NN + src], 1);
}

// exclusive scan of 4096 counts per type; one block per type
__global__ void scan_k() {
    int j = blockIdx.x, tid = threadIdx.x;
    __shared__ int sh[1024];
    __shared__ int carry_sh;
    if (tid == 0) carry_sh = 0;
    __syncthreads();
    for (int ch = 0; ch < 4; ch++) {
        int idx = ch * 1024 + tid;
        int v = g_cnt[j * NN + idx];
        sh[tid] = v;
        __syncthreads();
        for (int off = 1; off < 1024; off <<= 1) {
            int t = (tid >= off) ? sh[tid - off] : 0;
            __syncthreads();
            sh[tid] += t;
            __syncthreads();
        }
        int incl = sh[tid];
        int carry = carry_sh;
        int excl = carry + incl - v;
        g_rowptr[j * (NN + 1) + idx] = excl;
        g_cursor[j * NN + idx] = excl;
        __syncthreads();
        if (tid == 1023) carry_sh = carry + incl;
        __syncthreads();
    }
    if (tid == 1023) g_rowptr[j * (NN + 1) + NN] = carry_sh;
}

__global__ void scatter_k(const int* __restrict__ edge_index,
                          const float* __restrict__ edge_value) {
    int gid = blockIdx.x * blockDim.x + threadIdx.x;
    if (gid >= TT * EE) return;
    int j = gid / EE, e = gid - j * EE;
    int src = edge_index[j * 2 * EE + e];
    int dst = edge_index[j * 2 * EE + EE + e];
    float v = edge_value[j * EE + e];
    int pos = atomicAdd(&g_cursor[j * NN + src], 1);
    g_dst [j * EE + pos] = dst;
    g_valv[j * EE + pos] = v;
}

// XW = X @ gcn_w : [4096,512] @ [512,128] -> [4096,128]
// tile M=32, full N=128; 256 threads: (cx 0..31 -> 4 cols, cy 0..7 -> 4 rows)
__global__ void __launch_bounds__(256) gemm_k(const float* __restrict__ X,
                                              const float* __restrict__ Wt) {
    __shared__ float Xs[32][32];
    __shared__ float Ws[32][WOUT];
    int tid = threadIdx.x;
    int cx = tid & 31;
    int cy = tid >> 5;
    int row0 = blockIdx.x * 32;
    float acc[4][4];
#pragma unroll
    for (int i = 0; i < 4; i++)
#pragma unroll
        for (int k = 0; k < 4; k++) acc[i][k] = 0.f;

    for (int k0 = 0; k0 < WIN; k0 += 32) {
        // load Xs: 32x32 = 1024 / 256 = 4 per thread
#pragma unroll
        for (int i = 0; i < 4; i++) {
            int li = tid + i * 256;
            int r = li >> 5, c = li & 31;
            Xs[r][c] = X[(row0 + r) * WIN + k0 + c];
        }
        // load Ws: 32x128 floats = 1024 float4 / 256 = 4 per thread
#pragma unroll
        for (int i = 0; i < 4; i++) {
            int li = tid + i * 256;
            int r = li >> 5, c4 = li & 31;
            *(float4*)&Ws[r][c4 * 4] = *(const float4*)&Wt[(k0 + r) * WOUT + c4 * 4];
        }
        __syncthreads();
#pragma unroll
        for (int kk = 0; kk < 32; kk++) {
            float xv[4];
#pragma unroll
            for (int i = 0; i < 4; i++) xv[i] = Xs[cy * 4 + i][kk];
            float4 wv = *(float4*)&Ws[kk][cx * 4];
#pragma unroll
            for (int i = 0; i < 4; i++) {
                acc[i][0] += xv[i] * wv.x;
                acc[i][1] += xv[i] * wv.y;
                acc[i][2] += xv[i] * wv.z;
                acc[i][3] += xv[i] * wv.w;
            }
        }
        __syncthreads();
    }
#pragma unroll
    for (int i = 0; i < 4; i++) {
        float4 o = make_float4(acc[i][0], acc[i][1], acc[i][2], acc[i][3]);
        *(float4*)&g_XW[(row0 + cy * 4 + i) * WOUT + cx * 4] = o;
    }
}

// per-type row sums of A_j
__global__ void rs_k() {
    int gid = blockIdx.x * blockDim.x + threadIdx.x;
    if (gid >= TT * NN) return;
    int j = gid / NN, r = gid - j * NN;
    int s = g_rowptr[j * (NN + 1) + r], e = g_rowptr[j * (NN + 1) + r + 1];
    const float* vp = g_valv + j * EE;
    float acc = 0.f;
    for (int k = s; k < e; k++) acc += vp[k];
    g_rs[gid] = acc;
}

// s2[c] = rowsum(Q2_c), t3[c] = rowsum(Q3_c)
__global__ void s2t3_k() {
    int gid = blockIdx.x * blockDim.x + threadIdx.x;
    if (gid >= CC * NN) return;
    int c = gid >> 12, r = gid & (NN - 1);
    float s2 = 0.f, t3 = 0.f;
#pragma unroll
    for (int j = 0; j < TT; j++) {
        float rs = g_rs[j * NN + r];
        s2 += g_f2[c * TT + j] * rs;
        t3 += g_f3[c * TT + j] * rs;
    }
    g_s2[gid] = s2;
    g_t3[gid] = t3;
}

// u[c] = Q2_c @ t3[c]
__global__ void u_k() {
    int gid = blockIdx.x * blockDim.x + threadIdx.x;
    if (gid >= CC * NN) return;
    int c = gid >> 12, r = gid & (NN - 1);
    float acc = 0.f;
#pragma unroll
    for (int j = 0; j < TT; j++) {
        float f = g_f2[c * TT + j];
        int s = g_rowptr[j * (NN + 1) + r], e = g_rowptr[j * (NN + 1) + r + 1];
        const int* dp = g_dst + j * EE;
        const float* vp = g_valv + j * EE;
        for (int k = s; k < e; k++)
            acc += f * vp[k] * g_t3[c * NN + dp[k]];
    }
    g_u[gid] = acc;
}

// Stage A: Y3[c] = Q3_c @ XW  (full rows; XW shared across channels)
__global__ void __launch_bounds__(256) stageA_k() {
    int wid = (blockIdx.x << 3) + (threadIdx.x >> 5);
    if (wid >= NN) return;
    int lane = threadIdx.x & 31;
    int colb = lane * 4;
    float4 a0 = make_float4(0, 0, 0, 0), a1 = make_float4(0, 0, 0, 0);
#pragma unroll
    for (int j = 0; j < TT; j++) {
        float c0 = g_f3[0 * TT + j], c1 = g_f3[1 * TT + j];
        int s = g_rowptr[j * (NN + 1) + wid], e = g_rowptr[j * (NN + 1) + wid + 1];
        const int* dp = g_dst + j * EE;
        const float* vp = g_valv + j * EE;
        for (int k = s; k < e; k++) {
            int d = dp[k];
            float v = vp[k];
            float4 x = *(const float4*)&g_XW[d * WOUT + colb];
            float w0 = c0 * v, w1 = c1 * v;
            a0.x += w0 * x.x; a0.y += w0 * x.y; a0.z += w0 * x.z; a0.w += w0 * x.w;
            a1.x += w1 * x.x; a1.y += w1 * x.y; a1.z += w1 * x.z; a1.w += w1 * x.w;
        }
    }
    *(float4*)&g_Y3[0 * NN * WOUT + wid * WOUT + colb] = a0;
    *(float4*)&g_Y3[1 * NN * WOUT + wid * WOUT + colb] = a1;
}

// Stage B: Y2[c] = Q2_c @ Y3[c]  (full rows, both channels per warp)
__global__ void __launch_bounds__(256) stageB_k() {
    int wid = (blockIdx.x << 3) + (threadIdx.x >> 5);
    if (wid >= NN) return;
    int lane = threadIdx.x & 31;
    int colb = lane * 4;
    float4 a0 = make_float4(0, 0, 0, 0), a1 = make_float4(0, 0, 0, 0);
#pragma unroll
    for (int j = 0; j < TT; j++) {
        float c0 = g_f2[0 * TT + j], c1 = g_f2[1 * TT + j];
        int s = g_rowptr[j * (NN + 1) + wid], e = g_rowptr[j * (NN + 1) + wid + 1];
        const int* dp = g_dst + j * EE;
        const float* vp = g_valv + j * EE;
        for (int k = s; k < e; k++) {
            int d = dp[k];
            float v = vp[k];
            float4 y0 = *(const float4*)&g_Y3[0 * NN * WOUT + d * WOUT + colb];
            float4 y1 = *(const float4*)&g_Y3[1 * NN * WOUT + d * WOUT + colb];
            float w0 = c0 * v, w1 = c1 * v;
            a0.x += w0 * y0.x; a0.y += w0 * y0.y; a0.z += w0 * y0.z; a0.w += w0 * y0.w;
            a1.x += w1 * y1.x; a1.y += w1 * y1.y; a1.z += w1 * y1.z; a1.w += w1 * y1.w;
        }
    }
    *(float4*)&g_Y2[0 * NN * WOUT + wid * WOUT + colb] = a0;
    *(float4*)&g_Y2[1 * NN * WOUT + wid * WOUT + colb] = a1;
}

// Stage C: target rows only. z = dinv2*dinv1*(Q1_c @ Y2[c])[row], relu(z + b)
__global__ void __launch_bounds__(256) stageC_k(const int* __restrict__ target,
                                                const float* __restrict__ gcn_b) {
    int w = (blockIdx.x << 3) + (threadIdx.x >> 5);
    if (w >= NT * CC) return;
    int t = w >> 1, c = w & 1;
    int lane = threadIdx.x & 31;
    int colb = lane * 4;
    int row = target[t];
    float4 acc = make_float4(0, 0, 0, 0);
    float d1 = 0.f, d2 = 0.f;
#pragma unroll
    for (int j = 0; j < TT; j++) {
        float cf = g_f1[c * TT + j];
        int s = g_rowptr[j * (NN + 1) + row], e = g_rowptr[j * (NN + 1) + row + 1];
        const int* dp = g_dst + j * EE;
        const float* vp = g_valv + j * EE;
        for (int k = s; k < e; k++) {
            int d = dp[k];
            float v = vp[k];
            float wv = cf * v;
            float4 y = *(const float4*)&g_Y2[c * NN * WOUT + d * WOUT + colb];
            acc.x += wv * y.x; acc.y += wv * y.y; acc.z += wv * y.z; acc.w += wv * y.w;
            d1 += wv * g_s2[c * NN + d];
            d2 += wv * g_u [c * NN + d];
        }
    }
    float inv1 = (d1 == 0.f) ? 0.f : 1.f / d1;
    float deg2 = inv1 * d2;
    float inv2 = (deg2 == 0.f) ? 0.f : 1.f / deg2;
    float sc = inv1 * inv2;
    float4 b = *(const float4*)&gcn_b[colb];
    float4 o;
    o.x = fmaxf(sc * acc.x + b.x, 0.f);
    o.y = fmaxf(sc * acc.y + b.y, 0.f);
    o.z = fmaxf(sc * acc.z + b.z, 0.f);
    o.w = fmaxf(sc * acc.w + b.w, 0.f);
    *(float4*)&g_Xt[t * (CC * WOUT) + c * WOUT + colb] = o;
}

// y = Xt @ lin_w + lin_b : [1024,256] @ [256,16]
__global__ void final_k(const float* __restrict__ lin_w,
                        const float* __restrict__ lin_b,
                        float* __restrict__ out) {
    int gid = blockIdx.x * blockDim.x + threadIdx.x;
    if (gid >= NT * NCLS) return;
    int t = gid >> 4, cls = gid & 15;
    float acc = lin_b[cls];
    const float* xr = g_Xt + t * (CC * WOUT);
#pragma unroll 8
    for (int k = 0; k < CC * WOUT; k++)
        acc += xr[k] * lin_w[k * NCLS + cls];
    out[gid] = acc;
}

// ---------------- launch ----------------
extern "C" void kernel_launch(void* const* d_in, const int* in_sizes, int n_in,
                              void* d_out, int out_size) {
    const int*   edge_index = (const int*)d_in[0];
    const float* edge_value = (const float*)d_in[1];
    const float* X          = (const float*)d_in[2];
    const int*   target_x   = (const int*)d_in[3];
    const float* w_l0_c1    = (const float*)d_in[4];
    const float* w_l0_c2    = (const float*)d_in[5];
    const float* w_l1_c1    = (const float*)d_in[6];
    const float* gcn_w      = (const float*)d_in[7];
    const float* gcn_b      = (const float*)d_in[8];
    const float* lin_w      = (const float*)d_in[9];
    const float* lin_b      = (const float*)d_in[10];
    float* out = (float*)d_out;

    zero_k<<<(TT * NN + 255) / 256, 256>>>();
    softmax_k<<<1, 32>>>(w_l0_c1, w_l0_c2, w_l1_c1);
    count_k<<<(TT * EE + 255) / 256, 256>>>(edge_index);
    scan_k<<<TT, 1024>>>();
    scatter_k<<<(TT * EE + 255) / 256, 256>>>(edge_index, edge_value);
    gemm_k<<<NN / 32, 256>>>(X, gcn_w);
    rs_k<<<(TT * NN + 255) / 256, 256>>>();
    s2t3_k<<<(CC * NN + 255) / 256, 256>>>();
    u_k<<<(CC * NN + 255) / 256, 256>>>();
    stageA_k<<<NN / 8, 256>>>();
    stageB_k<<<NN / 8, 256>>>();
    stageC_k<<<(NT * CC) / 8, 256>>>(target_x, gcn_b);
    final_k<<<(NT * NCLS + 255) / 256, 256>>>(lin_w, lin_b, out);
}